// round 2
// baseline (speedup 1.0000x reference)
#include <cuda_runtime.h>

#define IMG_H 4200
#define IMG_W 3200
#define HF 84
#define WF 64
#define NB 8
#define STRIDE_PX 50
#define TILE_ELEMS 2500   // 50*50

// scratch: conv1 output feats [NB, 2, HF, WF]  (344 KB)
__device__ float g_feats[NB * 2 * HF * WF];

// ---------------------------------------------------------------------------
// Kernel 1: 50x50 stride-50 VALID conv, 1->2 channels.
// Non-overlapping patches: each output = dot(2500-elem patch, weights) + bias.
// Persistent blocks: per-thread weights cached in registers once, then
// grid-stride over all 43008 tiles. One 256-thread block per tile iteration.
// ---------------------------------------------------------------------------
__global__ __launch_bounds__(256) void conv1_kernel(const float* __restrict__ X,
                                                    const float* __restrict__ w,
                                                    const float* __restrict__ b)
{
    const int t = threadIdx.x;

    // Per-thread fixed element indices i = t + 256*j, j = 0..9 (2500 elems).
    float w0[10], w1[10];
    int   off[10];
#pragma unroll
    for (int j = 0; j < 10; j++) {
        int i = t + j * 256;
        bool ok = (i < TILE_ELEMS);
        w0[j]  = ok ? w[i]              : 0.0f;   // channel 0 weights [0..2499]
        w1[j]  = ok ? w[TILE_ELEMS + i] : 0.0f;   // channel 1 weights
        off[j] = ok ? ((i / 50) * IMG_W + (i % 50)) : 0;  // safe dummy offset 0
    }
    const float b0 = b[0], b1 = b[1];

    __shared__ float red0[8];
    __shared__ float red1[8];

    const int total_tiles = NB * HF * WF;  // 43008
    for (int tile = blockIdx.x; tile < total_tiles; tile += gridDim.x) {
        const int tx = tile % WF;
        const int ty = (tile / WF) % HF;
        const int n  = tile / (WF * HF);

        const float* xp = X + (size_t)n * IMG_H * IMG_W
                            + (size_t)(ty * STRIDE_PX) * IMG_W
                            + tx * STRIDE_PX;

        float a0 = 0.0f, a1 = 0.0f;
#pragma unroll
        for (int j = 0; j < 10; j++) {
            // invalid lanes have w==0, off==0 (in-bounds) -> contributes 0
            float xv = __ldg(xp + off[j]);
            a0 += xv * w0[j];
            a1 += xv * w1[j];
        }

        // warp reduce
#pragma unroll
        for (int s = 16; s > 0; s >>= 1) {
            a0 += __shfl_down_sync(0xffffffffu, a0, s);
            a1 += __shfl_down_sync(0xffffffffu, a1, s);
        }
        const int warp = t >> 5;
        if ((t & 31) == 0) { red0[warp] = a0; red1[warp] = a1; }
        __syncthreads();
        if (t == 0) {
            float s0 = 0.0f, s1 = 0.0f;
#pragma unroll
            for (int k = 0; k < 8; k++) { s0 += red0[k]; s1 += red1[k]; }
            g_feats[((n * 2 + 0) * HF + ty) * WF + tx] = s0 + b0;
            g_feats[((n * 2 + 1) * HF + ty) * WF + tx] = s1 + b1;
        }
        __syncthreads();  // protect red[] reuse next tile
    }
}

// ---------------------------------------------------------------------------
// Kernel 2: fused head. One thread per (n, y, x, anchor).
//   - 3x3 SAME box conv (thread computes its anchor's 4 offset channels)
//   - 3x3 SAME cls conv + softmax over 2 channels -> mask
//   - anchors + offsets, clip, mask-multiply, float4 coalesced store
// ---------------------------------------------------------------------------
__global__ __launch_bounds__(256) void head_kernel(const float* __restrict__ box_w,
                                                   const float* __restrict__ box_b,
                                                   const float* __restrict__ cls_w,
                                                   const float* __restrict__ cls_b,
                                                   float4* __restrict__ out)
{
    __shared__ float s_bw[36 * 18];  // box_w [36,2,3,3]
    __shared__ float s_bb[36];
    __shared__ float s_cw[36];       // cls_w [2,2,3,3]
    __shared__ float s_cb[2];

    for (int i = threadIdx.x; i < 36 * 18; i += blockDim.x) s_bw[i] = box_w[i];
    if (threadIdx.x < 36) {
        s_bb[threadIdx.x] = box_b[threadIdx.x];
        s_cw[threadIdx.x] = cls_w[threadIdx.x];
    }
    if (threadIdx.x < 2) s_cb[threadIdx.x] = cls_b[threadIdx.x];
    __syncthreads();

    const int t = blockIdx.x * blockDim.x + threadIdx.x;  // grid sized exactly
    const int a   = t % 9;
    const int pos = t / 9;
    const int x = pos % WF;
    const int y = (pos / WF) % HF;
    const int n = pos / (WF * HF);

    // Gather 3x3x2 neighborhood (zero-padded SAME)
    float f[18];
#pragma unroll
    for (int ic = 0; ic < 2; ic++) {
#pragma unroll
        for (int dy = 0; dy < 3; dy++) {
#pragma unroll
            for (int dx = 0; dx < 3; dx++) {
                const int yy = y + dy - 1;
                const int xx = x + dx - 1;
                float v = 0.0f;
                if (yy >= 0 && yy < HF && xx >= 0 && xx < WF)
                    v = g_feats[((n * 2 + ic) * HF + yy) * WF + xx];
                f[ic * 9 + dy * 3 + dx] = v;
            }
        }
    }

    // cls conv + softmax over channel axis (2 channels), threshold on p1
    float c0 = s_cb[0], c1 = s_cb[1];
#pragma unroll
    for (int k = 0; k < 18; k++) {
        c0 += f[k] * s_cw[k];
        c1 += f[k] * s_cw[18 + k];
    }
    const float m  = fmaxf(c0, c1);
    const float e0 = __expf(c0 - m) /* fast */, e1 = __expf(c1 - m);
    const float p1 = e1 / (e0 + e1);
    const float mval = (p1 > 0.95f) ? 1.0f : 0.0f;

    // box conv: channels 4a..4a+3  (channel c -> anchor c/4, coord c%4)
    float off4[4];
#pragma unroll
    for (int k = 0; k < 4; k++) {
        const int o = a * 4 + k;
        float acc = s_bb[o];
        const float* wp = &s_bw[o * 18];
#pragma unroll
        for (int kk = 0; kk < 18; kk++) acc += f[kk] * wp[kk];
        off4[k] = acc;
    }

    // anchors: sizes {16,32,64} x ratios {0.5,1,2}; a = size_idx*3 + ratio_idx
    const float SZ[3] = {16.0f, 32.0f, 64.0f};
    const float RT[3] = {0.5f, 1.0f, 2.0f};
    const float s  = SZ[a / 3];
    const float r  = sqrtf(RT[a % 3]);
    const float wa = s / r;
    const float ha = s * r;
    const float gx = ((float)x + 0.5f) * (float)STRIDE_PX;
    const float gy = ((float)y + 0.5f) * (float)STRIDE_PX;

    float v0 = fminf(fmaxf(gx - wa * 0.5f + off4[0], 0.0f), (float)IMG_W);
    float v1 = fminf(fmaxf(gy - ha * 0.5f + off4[1], 0.0f), (float)IMG_H);
    float v2 = fminf(fmaxf(gx + wa * 0.5f + off4[2], 0.0f), (float)IMG_W);
    float v3 = fminf(fmaxf(gy + ha * 0.5f + off4[3], 0.0f), (float)IMG_H);

    out[t] = make_float4(v0 * mval, v1 * mval, v2 * mval, v3 * mval);
}

extern "C" void kernel_launch(void* const* d_in, const int* in_sizes, int n_in,
                              void* d_out, int out_size)
{
    const float* X      = (const float*)d_in[0];
    const float* conv_w = (const float*)d_in[1];
    const float* conv_b = (const float*)d_in[2];
    const float* box_w  = (const float*)d_in[3];
    const float* box_b  = (const float*)d_in[4];
    const float* cls_w  = (const float*)d_in[5];
    const float* cls_b  = (const float*)d_in[6];
    float4* out = (float4*)d_out;

    // 43008 tiles / 32 tiles-per-block = 1344 persistent blocks
    conv1_kernel<<<1344, 256>>>(X, conv_w, conv_b);
    // 8*84*64*9 = 387072 threads = exactly 1512 blocks of 256
    head_kernel<<<1512, 256>>>(box_w, box_b, cls_w, cls_b, out);
}

// round 3
// speedup vs baseline: 1.7041x; 1.7041x over previous
#include <cuda_runtime.h>

#define IMG_H 4200
#define IMG_W 3200
#define HF 84
#define WF 64
#define NB 8
#define STRIDE_PX 50
#define ROW_F2 (IMG_W / 2)      // 1600 float2 per image row
#define TILE_F2 1250            // 50*50/2 float2 per tile

// scratch: conv1 output feats [NB, 2, HF, WF]  (344 KB)
__device__ float g_feats[NB * 2 * HF * WF];

// ---------------------------------------------------------------------------
// Kernel 1: 50x50 stride-50 VALID conv, 1->2 ch. Non-overlapping patches.
// float2 loads (rows are 8B-aligned), per-thread register weights,
// 4 tiles batched per reduction round (same tile row, consecutive tx).
// Persistent: 1344 blocks x 8 groups of 4 tiles = 43008 tiles.
// ---------------------------------------------------------------------------
__global__ __launch_bounds__(256) void conv1_kernel(const float* __restrict__ X,
                                                    const float* __restrict__ w,
                                                    const float* __restrict__ b)
{
    const int t = threadIdx.x;

    // Per-thread fixed float2 indices p = t + 256*j, j=0..4  (1250 total)
    float2 w0[5], w1[5];
    int    off[5];
    const float2* wv0 = (const float2*)w;              // ch0: 1250 float2
    const float2* wv1 = (const float2*)(w + 2500);     // ch1
#pragma unroll
    for (int j = 0; j < 5; j++) {
        int p = t + j * 256;
        bool ok = (p < TILE_F2);
        w0[j]  = ok ? wv0[p] : make_float2(0.f, 0.f);
        w1[j]  = ok ? wv1[p] : make_float2(0.f, 0.f);
        off[j] = ok ? ((p / 25) * ROW_F2 + (p % 25)) : 0;   // row*1600 + col2
    }
    const float b0 = b[0], b1 = b[1];

    __shared__ float red[8 * 8];   // [warp][tile*2+ch]

    const int total_groups = NB * HF * WF / 4;  // 10752
    for (int g = blockIdx.x; g < total_groups; g += gridDim.x) {
        const int tile0 = g * 4;                 // 4 consecutive tx, same (n,ty)
        const int tx0 = tile0 % WF;
        const int ty  = (tile0 / WF) % HF;
        const int n   = tile0 / (WF * HF);

        // base in float2 units; tile step along x = 25 float2
        const float2* base = (const float2*)X
            + (size_t)n * (IMG_H * ROW_F2)
            + (size_t)(ty * STRIDE_PX) * ROW_F2
            + tx0 * 25;

        float a[8] = {0.f, 0.f, 0.f, 0.f, 0.f, 0.f, 0.f, 0.f};  // [tile][ch]
#pragma unroll
        for (int j = 0; j < 5; j++) {
#pragma unroll
            for (int k = 0; k < 4; k++) {
                float2 xv = __ldg(base + k * 25 + off[j]);
                a[k * 2 + 0] += xv.x * w0[j].x + xv.y * w0[j].y;
                a[k * 2 + 1] += xv.x * w1[j].x + xv.y * w1[j].y;
            }
        }

        // warp reduce all 8 accumulators (independent chains pipeline)
#pragma unroll
        for (int s = 16; s > 0; s >>= 1) {
#pragma unroll
            for (int k = 0; k < 8; k++)
                a[k] += __shfl_down_sync(0xffffffffu, a[k], s);
        }
        const int warp = t >> 5;
        if ((t & 31) == 0) {
#pragma unroll
            for (int k = 0; k < 8; k++) red[warp * 8 + k] = a[k];
        }
        __syncthreads();

        // final cross-warp reduce: 64 threads, octet per output
        if (t < 64) {
            const int o = t >> 3;          // tile*2+ch (0..7)
            const int k = t & 7;           // warp index
            float v = red[k * 8 + o];
            v += __shfl_down_sync(0xffffffffu, v, 4, 8);
            v += __shfl_down_sync(0xffffffffu, v, 2, 8);
            v += __shfl_down_sync(0xffffffffu, v, 1, 8);
            if (k == 0) {
                const int tile = o >> 1, ch = o & 1;
                g_feats[((n * 2 + ch) * HF + ty) * WF + (tx0 + tile)] =
                    v + (ch ? b1 : b0);
            }
        }
        __syncthreads();   // protect red[] before next group
    }
}

// ---------------------------------------------------------------------------
// Kernel 2: fused head. ONE thread per (n,y,x): gathers 3x3x2 neighborhood
// once, computes cls softmax mask once, all 9 anchors' box convs, then
// warp-staged smem -> fully coalesced float4 output stores.
// ---------------------------------------------------------------------------
__global__ __launch_bounds__(256) void head_kernel(const float* __restrict__ box_w,
                                                   const float* __restrict__ box_b,
                                                   const float* __restrict__ cls_w,
                                                   const float* __restrict__ cls_b,
                                                   float4* __restrict__ out)
{
    __shared__ float  s_bw[36 * 18];       // box_w [36,2,3,3]
    __shared__ float  s_bb[36];
    __shared__ float  s_cw[36];            // cls_w [2,2,3,3]
    __shared__ float  s_cb[2];
    __shared__ float4 s_stage[8][32 * 9];  // per-warp output staging (36 KB)

    for (int i = threadIdx.x; i < 36 * 18; i += blockDim.x) s_bw[i] = box_w[i];
    if (threadIdx.x < 36) {
        s_bb[threadIdx.x] = box_b[threadIdx.x];
        s_cw[threadIdx.x] = cls_w[threadIdx.x];
    }
    if (threadIdx.x < 2) s_cb[threadIdx.x] = cls_b[threadIdx.x];
    __syncthreads();

    const int pos = blockIdx.x * blockDim.x + threadIdx.x;  // exact grid: 43008
    const int x = pos % WF;
    const int y = (pos / WF) % HF;
    const int n = pos / (WF * HF);
    const int warp = threadIdx.x >> 5;
    const int lane = threadIdx.x & 31;

    // Gather 3x3x2 neighborhood (zero-padded SAME)
    float f[18];
#pragma unroll
    for (int ic = 0; ic < 2; ic++) {
#pragma unroll
        for (int dy = 0; dy < 3; dy++) {
#pragma unroll
            for (int dx = 0; dx < 3; dx++) {
                const int yy = y + dy - 1;
                const int xx = x + dx - 1;
                float v = 0.0f;
                if (yy >= 0 && yy < HF && xx >= 0 && xx < WF)
                    v = g_feats[((n * 2 + ic) * HF + yy) * WF + xx];
                f[ic * 9 + dy * 3 + dx] = v;
            }
        }
    }

    // cls conv + 2-channel softmax, threshold mask (computed once)
    float c0 = s_cb[0], c1 = s_cb[1];
#pragma unroll
    for (int k = 0; k < 18; k++) {
        c0 += f[k] * s_cw[k];
        c1 += f[k] * s_cw[18 + k];
    }
    const float m  = fmaxf(c0, c1);
    const float e0 = __expf(c0 - m), e1 = __expf(c1 - m);
    const float p1 = e1 / (e0 + e1);
    const float mval = (p1 > 0.95f) ? 1.0f : 0.0f;

    const float gx = ((float)x + 0.5f) * (float)STRIDE_PX;
    const float gy = ((float)y + 0.5f) * (float)STRIDE_PX;
    const float SZ[3] = {16.0f, 32.0f, 64.0f};
    const float RI[3] = {0.70710678118654752f, 1.0f, 1.41421356237309505f}; // sqrt(ratio)

    // all 9 anchors
#pragma unroll
    for (int a = 0; a < 9; a++) {
        float o0 = s_bb[a * 4 + 0], o1 = s_bb[a * 4 + 1];
        float o2 = s_bb[a * 4 + 2], o3 = s_bb[a * 4 + 3];
        const float* wp = &s_bw[a * 4 * 18];
#pragma unroll
        for (int kk = 0; kk < 18; kk++) {
            const float fv = f[kk];
            o0 += fv * wp[kk];
            o1 += fv * wp[18 + kk];
            o2 += fv * wp[36 + kk];
            o3 += fv * wp[54 + kk];
        }
        const float s  = SZ[a / 3];
        const float r  = RI[a % 3];
        const float wa = (s / r) * 0.5f;
        const float ha = (s * r) * 0.5f;
        float v0 = fminf(fmaxf(gx - wa + o0, 0.0f), (float)IMG_W);
        float v1 = fminf(fmaxf(gy - ha + o1, 0.0f), (float)IMG_H);
        float v2 = fminf(fmaxf(gx + wa + o2, 0.0f), (float)IMG_W);
        float v3 = fminf(fmaxf(gy + ha + o3, 0.0f), (float)IMG_H);
        s_stage[warp][lane * 9 + a] =
            make_float4(v0 * mval, v1 * mval, v2 * mval, v3 * mval);
    }
    __syncwarp();

    // coalesced copy-out: warp's 32 positions = 288 contiguous float4
    float4* wout = out + (size_t)(blockIdx.x * blockDim.x + warp * 32) * 9;
#pragma unroll
    for (int i = 0; i < 9; i++)
        wout[lane + 32 * i] = s_stage[warp][lane + 32 * i];
}

extern "C" void kernel_launch(void* const* d_in, const int* in_sizes, int n_in,
                              void* d_out, int out_size)
{
    const float* X      = (const float*)d_in[0];
    const float* conv_w = (const float*)d_in[1];
    const float* conv_b = (const float*)d_in[2];
    const float* box_w  = (const float*)d_in[3];
    const float* box_b  = (const float*)d_in[4];
    const float* cls_w  = (const float*)d_in[5];
    const float* cls_b  = (const float*)d_in[6];
    float4* out = (float4*)d_out;

    // 10752 groups of 4 tiles / 1344 persistent blocks = 8 groups each
    conv1_kernel<<<1344, 256>>>(X, conv_w, conv_b);
    // 43008 positions = exactly 168 blocks of 256
    head_kernel<<<168, 256>>>(box_w, box_b, cls_w, cls_b, out);
}

// round 4
// speedup vs baseline: 1.8594x; 1.0911x over previous
#include <cuda_runtime.h>

#define IMG_H 4200
#define IMG_W 3200
#define HF 84
#define WF 64
#define NB 8
#define STRIDE_PX 50
#define ROW_F2 (IMG_W / 2)      // 1600 float2 per image row
#define TILE_F2 1250            // 50*50/2 float2 per tile

// scratch: conv1 output feats [NB, 2, HF, WF]  (344 KB)
__device__ float g_feats[NB * 2 * HF * WF];

// ---------------------------------------------------------------------------
// Kernel 1: 50x50 stride-50 VALID conv, 1->2 ch (non-overlapping patches).
// 8 tiles per round (one row-octet of tx), 40 LDG.64 in flight per thread-
// round, register weights, double-buffered cross-warp reduce (1 bar/round),
// single-wave persistent grid (592 = 148*4 blocks).
// ---------------------------------------------------------------------------
__global__ __launch_bounds__(256, 4) void conv1_kernel(const float* __restrict__ X,
                                                       const float* __restrict__ w,
                                                       const float* __restrict__ b)
{
    const int t = threadIdx.x;

    // Per-thread fixed float2 indices p = t + 256*j, j=0..4 (1250 total)
    float2 w0[5], w1[5];
    int    off[5];
    const float2* wv0 = (const float2*)w;              // ch0: 1250 float2
    const float2* wv1 = (const float2*)(w + 2500);     // ch1
#pragma unroll
    for (int j = 0; j < 5; j++) {
        int p = t + j * 256;
        bool ok = (p < TILE_F2);
        w0[j]  = ok ? wv0[p] : make_float2(0.f, 0.f);
        w1[j]  = ok ? wv1[p] : make_float2(0.f, 0.f);
        off[j] = ok ? ((p / 25) * ROW_F2 + (p % 25)) : 0;   // row*1600 + col2
    }
    const float b0 = b[0], b1 = b[1];

    __shared__ float red[2][8][16];   // [buf][warp][tile*2+ch]

    const int warp = t >> 5;
    const int total_rounds = NB * HF * WF / 8;  // 5376 rounds of 8 tiles
    int buf = 0;

    for (int r = blockIdx.x; r < total_rounds; r += gridDim.x, buf ^= 1) {
        const int tile0 = r * 8;                 // 8 consecutive tx, same (n,ty)
        const int tx0 = tile0 % WF;              // 0,8,...,56
        const int ty  = (tile0 / WF) % HF;
        const int n   = tile0 / (WF * HF);

        const float2* base = (const float2*)X
            + (size_t)n * (IMG_H * ROW_F2)
            + (size_t)(ty * STRIDE_PX) * ROW_F2
            + tx0 * 25;

        float a[16];
#pragma unroll
        for (int k = 0; k < 16; k++) a[k] = 0.f;

#pragma unroll
        for (int j = 0; j < 5; j++) {
#pragma unroll
            for (int k = 0; k < 8; k++) {
                float2 xv = __ldg(base + k * 25 + off[j]);
                a[k * 2 + 0] += xv.x * w0[j].x + xv.y * w0[j].y;
                a[k * 2 + 1] += xv.x * w1[j].x + xv.y * w1[j].y;
            }
        }

        // warp reduce: 16 independent shfl chains
#pragma unroll
        for (int s = 16; s > 0; s >>= 1) {
#pragma unroll
            for (int k = 0; k < 16; k++)
                a[k] += __shfl_down_sync(0xffffffffu, a[k], s);
        }
        if ((t & 31) == 0) {
#pragma unroll
            for (int k = 0; k < 16; k++) red[buf][warp][k] = a[k];
        }
        __syncthreads();   // only barrier this round (buffers alternate)

        // cross-warp final: 128 threads, one octet of warps per output
        if (t < 128) {
            const int o = t >> 3;          // output 0..15 = tile*2+ch
            const int k = t & 7;           // warp index
            float v = red[buf][k][o];
            v += __shfl_down_sync(0xffffffffu, v, 4, 8);
            v += __shfl_down_sync(0xffffffffu, v, 2, 8);
            v += __shfl_down_sync(0xffffffffu, v, 1, 8);
            if (k == 0) {
                const int tile = o >> 1, ch = o & 1;
                g_feats[((n * 2 + ch) * HF + ty) * WF + (tx0 + tile)] =
                    v + (ch ? b1 : b0);
            }
        }
    }
}

// ---------------------------------------------------------------------------
// Kernel 2: fused head. Block = 128 threads = 2 feature rows x 64 cols of one
// image (42 blocks/image -> never straddles n or HF). Feats neighborhood
// staged in smem (4 rows x 64 x 2ch), weights in smem, one thread per
// position computes mask + all 9 anchors, coalesced staged float4 output.
// ---------------------------------------------------------------------------
__global__ __launch_bounds__(128) void head_kernel(const float* __restrict__ box_w,
                                                   const float* __restrict__ box_b,
                                                   const float* __restrict__ cls_w,
                                                   const float* __restrict__ cls_b,
                                                   float4* __restrict__ out)
{
    __shared__ float  s_bw[36 * 18];       // box_w [36,2,3,3]
    __shared__ float  s_bb[36];
    __shared__ float  s_cw[36];            // cls_w [2,2,3,3]
    __shared__ float  s_cb[2];
    __shared__ float  s_f[2][4][64];       // feats ch x rows(y0-1..y0+2) x cols
    __shared__ float4 s_stage[128 * 9];    // output staging (18 KB)

    const int tid = threadIdx.x;

    for (int i = tid; i < 36 * 18; i += 128) s_bw[i] = box_w[i];
    if (tid < 36) {
        s_bb[tid] = box_b[tid];
        s_cw[tid] = cls_w[tid];
    }
    if (tid < 2) s_cb[tid] = cls_b[tid];

    const int n  = blockIdx.x / 42;
    const int y0 = (blockIdx.x % 42) * 2;   // block covers rows y0, y0+1

    // stage feats rows y0-1 .. y0+2 (zero-padded), 512 elements / 128 threads
#pragma unroll
    for (int i = 0; i < 4; i++) {
        const int e  = tid + i * 128;       // 0..511
        const int xx = e & 63;
        const int rr = (e >> 6) & 3;        // 0..3 -> row y0-1+rr
        const int ic = e >> 8;              // 0..1
        const int yy = y0 - 1 + rr;
        float v = 0.0f;
        if (yy >= 0 && yy < HF)
            v = g_feats[((n * 2 + ic) * HF + yy) * WF + xx];
        s_f[ic][rr][xx] = v;
    }
    __syncthreads();

    const int x  = tid & 63;
    const int ly = tid >> 6;                // 0 or 1
    const int y  = y0 + ly;

    // gather 3x3x2 neighborhood from smem (x edges zero-padded)
    float f[18];
#pragma unroll
    for (int ic = 0; ic < 2; ic++) {
#pragma unroll
        for (int dy = 0; dy < 3; dy++) {
#pragma unroll
            for (int dx = 0; dx < 3; dx++) {
                const int xx = x + dx - 1;
                float v = 0.0f;
                if (xx >= 0 && xx < WF) v = s_f[ic][ly + dy][xx];
                f[ic * 9 + dy * 3 + dx] = v;
            }
        }
    }

    // cls conv + 2-channel softmax threshold (once per position)
    float c0 = s_cb[0], c1 = s_cb[1];
#pragma unroll
    for (int k = 0; k < 18; k++) {
        c0 += f[k] * s_cw[k];
        c1 += f[k] * s_cw[18 + k];
    }
    const float m  = fmaxf(c0, c1);
    const float e0 = __expf(c0 - m), e1 = __expf(c1 - m);
    const float p1 = e1 / (e0 + e1);
    const float mval = (p1 > 0.95f) ? 1.0f : 0.0f;

    const float gx = ((float)x + 0.5f) * (float)STRIDE_PX;
    const float gy = ((float)y + 0.5f) * (float)STRIDE_PX;
    const float SZ[3] = {16.0f, 32.0f, 64.0f};
    const float RI[3] = {0.70710678118654752f, 1.0f, 1.41421356237309505f};

#pragma unroll
    for (int a = 0; a < 9; a++) {
        float o0 = s_bb[a * 4 + 0], o1 = s_bb[a * 4 + 1];
        float o2 = s_bb[a * 4 + 2], o3 = s_bb[a * 4 + 3];
        const float* wp = &s_bw[a * 4 * 18];
#pragma unroll
        for (int kk = 0; kk < 18; kk++) {
            const float fv = f[kk];
            o0 += fv * wp[kk];
            o1 += fv * wp[18 + kk];
            o2 += fv * wp[36 + kk];
            o3 += fv * wp[54 + kk];
        }
        const float s  = SZ[a / 3];
        const float r  = RI[a % 3];
        const float wa = (s / r) * 0.5f;
        const float ha = (s * r) * 0.5f;
        float v0 = fminf(fmaxf(gx - wa + o0, 0.0f), (float)IMG_W);
        float v1 = fminf(fmaxf(gy - ha + o1, 0.0f), (float)IMG_H);
        float v2 = fminf(fmaxf(gx + wa + o2, 0.0f), (float)IMG_W);
        float v3 = fminf(fmaxf(gy + ha + o3, 0.0f), (float)IMG_H);
        s_stage[tid * 9 + a] =
            make_float4(v0 * mval, v1 * mval, v2 * mval, v3 * mval);
    }
    __syncthreads();

    // coalesced copy-out: block's 128 positions = 1152 contiguous float4
    float4* bout = out + (size_t)blockIdx.x * 128 * 9;
#pragma unroll
    for (int i = 0; i < 9; i++)
        bout[tid + 128 * i] = s_stage[tid + 128 * i];
}

extern "C" void kernel_launch(void* const* d_in, const int* in_sizes, int n_in,
                              void* d_out, int out_size)
{
    const float* X      = (const float*)d_in[0];
    const float* conv_w = (const float*)d_in[1];
    const float* conv_b = (const float*)d_in[2];
    const float* box_w  = (const float*)d_in[3];
    const float* box_b  = (const float*)d_in[4];
    const float* cls_w  = (const float*)d_in[5];
    const float* cls_b  = (const float*)d_in[6];
    float4* out = (float4*)d_out;

    // single-wave persistent: 148 SMs x 4 blocks, grid-stride over 5376 rounds
    conv1_kernel<<<592, 256>>>(X, conv_w, conv_b);
    // 43008 positions / 128 = 336 blocks (42 per image)
    head_kernel<<<336, 128>>>(box_w, box_b, cls_w, cls_b, out);
}